// round 8
// baseline (speedup 1.0000x reference)
#include <cuda_runtime.h>

// Problem constants
#define SN 4096
#define HN 1024
#define BN 4
#define RN 16
#define ROWS_TOT (BN * SN)     // 16384

// k1 tiling
#define KQ4 4                  // split-K factor
#define KQLEN (HN / KQ4)       // 256 k per split
#define KC 32                  // k per chunk
#define NCH (KQLEN / KC)       // 8 chunks
#define BM 256                 // rows per CTA
#define PTA 36                 // A pitch (floats)
#define PWQ 260                // W pitch (floats) for full k-quarter row
#define SMEM_K1 ((2 * BM * PTA + 33 * PWQ) * 4)   // 108048 B

// ---------------- scratch (device globals; no allocation) ----------------
__device__ float g_part[KQ4 * 33 * ROWS_TOT];  // split-K partials [kq][j][row]
__device__ float g_Pp[BN * SN * RN];           // plain P [b][s][r]
__device__ float g_Ur[BN * 8 * SN * 2];        // U r-pair interleaved [b][rp][t][2]
__device__ float g_V[BN * SN];                 // bias-term dot [b][t]

// packed f32x2 FMA (SASS FFMA2)
__device__ __forceinline__ float2 ffma2(float2 a, float2 b, float2 c) {
    float2 d;
    asm("fma.rn.f32x2 %0, %1, %2, %3;"
        : "=l"(*reinterpret_cast<unsigned long long*>(&d))
        : "l"(*reinterpret_cast<unsigned long long*>(&a)),
          "l"(*reinterpret_cast<unsigned long long*>(&b)),
          "l"(*reinterpret_cast<unsigned long long*>(&c)));
    return d;
}

__device__ __forceinline__ void cp16(void* smem_dst, const void* gmem_src) {
    unsigned sdst = (unsigned)__cvta_generic_to_shared(smem_dst);
    asm volatile("cp.async.cg.shared.global [%0], [%1], 16;"
                 :: "r"(sdst), "l"(gmem_src) : "memory");
}
__device__ __forceinline__ void cp_commit() {
    asm volatile("cp.async.commit_group;" ::: "memory");
}
__device__ __forceinline__ void cp_wait0() {
    asm volatile("cp.async.wait_group 0;" ::: "memory");
}

// =======================================================================
// kernel 1: split-K projection partials. grid (64, 4), 256 thr, occ 2.
//   W (33 x 256 incl. besum) preloaded ONCE into smem; only A is
//   double-buffered per chunk -> per-chunk wait covers A alone.
// =======================================================================
__global__ __launch_bounds__(256, 2)
void k1_proj(const float* __restrict__ hs,
             const float* __restrict__ wc,
             const float* __restrict__ we,
             const float* __restrict__ be) {
    extern __shared__ float smem[];
    float* As = smem;                        // [2][BM*PTA]
    float* Ws = smem + 2 * BM * PTA;         // [33][PWQ]

    const int tid = threadIdx.x;
    const int x = tid & 31;
    const int wid = tid >> 5;
    const int rh = wid & 1;
    const int g = wid >> 1;                  // n-group 0..3
    const int r0 = x + 32 * rh;              // base row; +64*m
    const int rowBase = blockIdx.x * BM;
    const int kq = blockIdx.y;
    const int kOff = kq * KQLEN;

    // ---- one-time W preload: rows 0..31 = wc|we (cp.async), row 32 = besum
    #pragma unroll
    for (int i = 0; i < 8; i++) {
        int idx = tid + 256 * i;             // 0..2047 float4
        int n = idx >> 6, c4 = idx & 63;     // 64 float4 per row
        const float* src = (n < 16)
            ? &wc[n * HN + kOff + c4 * 4]
            : &we[(n - 16) * HN + kOff + c4 * 4];
        cp16(&Ws[n * PWQ + c4 * 4], src);
    }
    cp_commit();
    {
        float s = 0.f;
        #pragma unroll
        for (int r = 0; r < RN; r++) s += be[r * HN + kOff + tid];
        Ws[32 * PWQ + tid] = s;
    }

    // ---- A staging (double buffer, A-only commit groups)
    auto stageA = [&](int c, int buf) {
        #pragma unroll
        for (int i = 0; i < 8; i++) {
            int idx = tid + 256 * i;
            int row = idx >> 3, k4 = idx & 7;
            cp16(&As[buf * BM * PTA + row * PTA + k4 * 4],
                 &hs[(size_t)(rowBase + row) * HN + kOff + c * KC + k4 * 4]);
        }
        cp_commit();
    };

    float2 acc[4][8];
    #pragma unroll
    for (int m = 0; m < 4; m++)
        #pragma unroll
        for (int n = 0; n < 8; n++) acc[m][n] = make_float2(0.f, 0.f);
    float2 vacc[4];
    #pragma unroll
    for (int m = 0; m < 4; m++) vacc[m] = make_float2(0.f, 0.f);

    stageA(0, 0);          // group 2 (after W group 1) — wait0 drains both at c=0

    for (int c = 0; c < NCH; c++) {
        cp_wait0();
        __syncthreads();
        if (c + 1 < NCH) stageA(c + 1, (c + 1) & 1);
        const int buf = c & 1;
        const float4* As4 = reinterpret_cast<const float4*>(&As[buf * BM * PTA]);
        const float4* Ws4 = reinterpret_cast<const float4*>(Ws);

        #pragma unroll
        for (int q = 0; q < 8; q++) {
            const int kidx = c * 8 + q;      // float4 index within k-quarter
            float4 w4[8];
            #pragma unroll
            for (int n = 0; n < 8; n++)
                w4[n] = Ws4[(g * 8 + n) * (PWQ / 4) + kidx];   // uniform
            float4 b4;
            if (g == 0) b4 = Ws4[32 * (PWQ / 4) + kidx];       // uniform

            #pragma unroll
            for (int m = 0; m < 4; m++) {
                float4 a4 = As4[(r0 + 64 * m) * (PTA / 4) + q];
                float2 alo = make_float2(a4.x, a4.y);
                float2 ahi = make_float2(a4.z, a4.w);
                #pragma unroll
                for (int n = 0; n < 8; n++) {
                    acc[m][n] = ffma2(alo, make_float2(w4[n].x, w4[n].y), acc[m][n]);
                    acc[m][n] = ffma2(ahi, make_float2(w4[n].z, w4[n].w), acc[m][n]);
                }
                if (g == 0) {
                    vacc[m] = ffma2(alo, make_float2(b4.x, b4.y), vacc[m]);
                    vacc[m] = ffma2(ahi, make_float2(b4.z, b4.w), vacc[m]);
                }
            }
        }
        __syncthreads();
    }

    // write partials (coalesced: 32 consecutive rows per warp)
    #pragma unroll
    for (int m = 0; m < 4; m++) {
        int row = rowBase + r0 + 64 * m;
        #pragma unroll
        for (int n = 0; n < 8; n++) {
            int j = g * 8 + n;
            g_part[(kq * 33 + j) * ROWS_TOT + row] = acc[m][n].x + acc[m][n].y;
        }
        if (g == 0)
            g_part[(kq * 33 + 32) * ROWS_TOT + row] = vacc[m].x + vacc[m].y;
    }
}

// =======================================================================
// k1_reduce: sum 4 split-K partials, epilogue, scatter to P / Ur / V.
// =======================================================================
__global__ __launch_bounds__(256)
void k1_reduce(const float* __restrict__ bc,
               const float* __restrict__ strength) {
    const int row = blockIdx.x * 256 + threadIdx.x;
    const int j = blockIdx.y;
    float v = 0.f;
    #pragma unroll
    for (int kq = 0; kq < KQ4; kq++)
        v += g_part[(kq * 33 + j) * ROWS_TOT + row];
    const int b = row >> 12;
    const int s = row & (SN - 1);
    if (j < 16) {
        g_Pp[(b * SN + s) * RN + j] = (v + bc[j]) * strength[j];
    } else if (j < 32) {
        int r = j - 16;
        g_Ur[(((b * 8) + (r >> 1)) * SN + s) * 2 + (r & 1)] = v;
    } else {
        g_V[b * SN + s] = v;
    }
}

// =======================================================================
// kernel 2: bias[b,s,t] = sum_r P[b,s,r]*U[b,r,t] + V[b,t]
//   Rule-pair packing: per s-step 4 uniform LDS.128 + 32 FFMA2 + 4 FADD
//   + 1 streaming STG.128.
// =======================================================================
#define K2_TB 1024
#define K2_SB 64

__global__ __launch_bounds__(256, 2)
void k2_outer(float* __restrict__ out) {
    __shared__ __align__(16) float4 Ps[K2_SB * 4];   // 4KB

    const int tid = threadIdx.x;
    const int w = tid >> 5;
    const int l = tid & 31;
    const int b = blockIdx.z;
    const int sB = blockIdx.y * K2_SB;
    const int t = blockIdx.x * K2_TB + w * 128 + l * 4;

    Ps[tid] = reinterpret_cast<const float4*>(&g_Pp[(b * SN + sB) * RN])[tid];

    float2 u2[8][4];
    #pragma unroll
    for (int rp = 0; rp < 8; rp++) {
        const float4* ub = reinterpret_cast<const float4*>(
            &g_Ur[((size_t)(b * 8 + rp) * SN + t) * 2]);
        float4 lo = ub[0], hi = ub[1];
        u2[rp][0] = make_float2(lo.x, lo.y);
        u2[rp][1] = make_float2(lo.z, lo.w);
        u2[rp][2] = make_float2(hi.x, hi.y);
        u2[rp][3] = make_float2(hi.z, hi.w);
    }

    float4 v4 = *reinterpret_cast<const float4*>(&g_V[b * SN + t]);

    __syncthreads();

    float* orow = out + (size_t)(b * SN + sB) * SN + t;

    #pragma unroll 2
    for (int si = 0; si < K2_SB; si++) {
        float4 q0 = Ps[si * 4 + 0], q1 = Ps[si * 4 + 1];
        float4 q2 = Ps[si * 4 + 2], q3 = Ps[si * 4 + 3];
        float2 p2[8] = {
            make_float2(q0.x, q0.y), make_float2(q0.z, q0.w),
            make_float2(q1.x, q1.y), make_float2(q1.z, q1.w),
            make_float2(q2.x, q2.y), make_float2(q2.z, q2.w),
            make_float2(q3.x, q3.y), make_float2(q3.z, q3.w)
        };

        float2 a0 = make_float2(v4.x, 0.f), a1 = make_float2(v4.y, 0.f);
        float2 a2 = make_float2(v4.z, 0.f), a3 = make_float2(v4.w, 0.f);
        #pragma unroll
        for (int rp = 0; rp < 8; rp++) {
            a0 = ffma2(p2[rp], u2[rp][0], a0);
            a1 = ffma2(p2[rp], u2[rp][1], a1);
            a2 = ffma2(p2[rp], u2[rp][2], a2);
            a3 = ffma2(p2[rp], u2[rp][3], a3);
        }

        __stcs(reinterpret_cast<float4*>(orow + (size_t)si * SN),
               make_float4(a0.x + a0.y, a1.x + a1.y, a2.x + a2.y, a3.x + a3.y));
    }
}

// ---------------- launch ----------------
extern "C" void kernel_launch(void* const* d_in, const int* in_sizes, int n_in,
                              void* d_out, int out_size) {
    const float* hs       = (const float*)d_in[0];
    const float* wc       = (const float*)d_in[1];
    const float* bc       = (const float*)d_in[2];
    const float* we       = (const float*)d_in[3];
    const float* be       = (const float*)d_in[4];
    const float* strength = (const float*)d_in[5];
    float* out = (float*)d_out;

    cudaFuncSetAttribute(k1_proj,
                         cudaFuncAttributeMaxDynamicSharedMemorySize, SMEM_K1);
    k1_proj<<<dim3(ROWS_TOT / BM, KQ4), 256, SMEM_K1>>>(hs, wc, we, be);
    k1_reduce<<<dim3(ROWS_TOT / 256, 33), 256>>>(bc, strength);
    k2_outer<<<dim3(SN / K2_TB, SN / K2_SB, BN), 256>>>(out);
}

// round 11
// speedup vs baseline: 1.0117x; 1.0117x over previous
#include <cuda_runtime.h>

// Problem constants
#define SN 4096
#define HN 1024
#define BN 4
#define RN 16
#define ROWS_TOT (BN * SN)     // 16384

// k1 tiling (split-K x2, BM=128, m=2 x n=8)
#define K1_BM 128
#define KC 32
#define PT 36
#define KHALF 512
#define NCH (KHALF / KC)       // 16 chunks

// ---------------- scratch (device globals; no allocation) ----------------
__device__ float g_part[2 * 33 * ROWS_TOT];    // split-K partials [kh][j][row]
__device__ float g_Pp[BN * SN * RN];           // plain P [b][s][r]
__device__ float g_Ur[BN * 8 * SN * 2];        // U r-pair interleaved [b][rp][t][2]
__device__ float g_V[BN * SN];                 // bias-term dot [b][t]

// packed f32x2 FMA
__device__ __forceinline__ float2 ffma2(float2 a, float2 b, float2 c) {
    float2 d;
    asm("fma.rn.f32x2 %0, %1, %2, %3;"
        : "=l"(*reinterpret_cast<unsigned long long*>(&d))
        : "l"(*reinterpret_cast<unsigned long long*>(&a)),
          "l"(*reinterpret_cast<unsigned long long*>(&b)),
          "l"(*reinterpret_cast<unsigned long long*>(&c)));
    return d;
}

__device__ __forceinline__ void cp16(void* smem_dst, const void* gmem_src) {
    unsigned sdst = (unsigned)__cvta_generic_to_shared(smem_dst);
    asm volatile("cp.async.cg.shared.global [%0], [%1], 16;"
                 :: "r"(sdst), "l"(gmem_src) : "memory");
}
__device__ __forceinline__ void cp_commit() {
    asm volatile("cp.async.commit_group;" ::: "memory");
}
__device__ __forceinline__ void cp_wait1() {
    asm volatile("cp.async.wait_group 1;" ::: "memory");
}
__device__ __forceinline__ void cp_wait0() {
    asm volatile("cp.async.wait_group 0;" ::: "memory");
}

// =======================================================================
// kernel 1: split-K projection partials. grid (128, 2), 256 thr, OCC 3.
//   Stage-before-wait: chunk c+1's cp.async issued before waiting on c.
//   FIX vs R9: last iteration drains with wait_group 0 (was wait_group 1,
//   which let the final chunk's copies still be in flight during compute).
// =======================================================================
__global__ __launch_bounds__(256, 3)
void k1_proj(const float* __restrict__ hs,
             const float* __restrict__ wc,
             const float* __restrict__ we,
             const float* __restrict__ be) {
    __shared__ float besum_s[KHALF];
    __shared__ __align__(16) float As[2][K1_BM * PT];
    __shared__ __align__(16) float Ws[2][32 * PT];

    const int tid = threadIdx.x;
    const int x = tid & 31;
    const int wid = tid >> 5;
    const int rh = wid & 1;
    const int g = wid >> 1;              // n-group 0..3
    const int r0 = x + 32 * rh;          // base row (+64 for m=1)
    const int rowBase = blockIdx.x * K1_BM;
    const int kh = blockIdx.y;
    const int kOff = kh * KHALF;

    // besum slice for this k-half
    #pragma unroll
    for (int j = 0; j < 2; j++) {
        int col = tid + 256 * j;
        float s = 0.f;
        #pragma unroll
        for (int r = 0; r < RN; r++) s += be[r * HN + kOff + col];
        besum_s[col] = s;
    }

    auto stage = [&](int c, int buf) {
        #pragma unroll
        for (int i = 0; i < 4; i++) {
            int idx = tid + 256 * i;
            int row = idx >> 3, k4 = idx & 7;
            cp16(&As[buf][row * PT + k4 * 4],
                 &hs[(size_t)(rowBase + row) * HN + kOff + c * KC + k4 * 4]);
        }
        {
            int n = tid >> 3, k4 = tid & 7;
            const float* src = (n < 16)
                ? &wc[n * HN + kOff + c * KC + k4 * 4]
                : &we[(n - 16) * HN + kOff + c * KC + k4 * 4];
            cp16(&Ws[buf][n * PT + k4 * 4], src);
        }
        cp_commit();
    };

    float2 acc[2][8];
    #pragma unroll
    for (int m = 0; m < 2; m++)
        #pragma unroll
        for (int n = 0; n < 8; n++) acc[m][n] = make_float2(0.f, 0.f);
    float2 vacc[2] = {make_float2(0.f, 0.f), make_float2(0.f, 0.f)};

    stage(0, 0);

    for (int c = 0; c < NCH; c++) {
        if (c + 1 < NCH) {
            stage(c + 1, (c + 1) & 1);   // deep prefetch
            cp_wait1();                  // chunk c resident, c+1 in flight
        } else {
            cp_wait0();                  // FINAL chunk: drain fully
        }
        __syncthreads();
        const int buf = c & 1;

        #pragma unroll
        for (int q = 0; q < 8; q++) {                  // 4 k per q
            float4 a0 = *reinterpret_cast<const float4*>(&As[buf][r0 * PT + 4 * q]);
            float4 a1 = *reinterpret_cast<const float4*>(&As[buf][(r0 + 64) * PT + 4 * q]);
            float2 a0lo = make_float2(a0.x, a0.y), a0hi = make_float2(a0.z, a0.w);
            float2 a1lo = make_float2(a1.x, a1.y), a1hi = make_float2(a1.z, a1.w);

            #pragma unroll
            for (int nh = 0; nh < 2; nh++) {           // n-halves: live w regs = 16
                #pragma unroll
                for (int n = 0; n < 4; n++) {
                    float4 w4 = *reinterpret_cast<const float4*>(
                        &Ws[buf][(g * 8 + nh * 4 + n) * PT + 4 * q]);   // uniform
                    int nn = nh * 4 + n;
                    acc[0][nn] = ffma2(a0lo, make_float2(w4.x, w4.y), acc[0][nn]);
                    acc[0][nn] = ffma2(a0hi, make_float2(w4.z, w4.w), acc[0][nn]);
                    acc[1][nn] = ffma2(a1lo, make_float2(w4.x, w4.y), acc[1][nn]);
                    acc[1][nn] = ffma2(a1hi, make_float2(w4.z, w4.w), acc[1][nn]);
                }
            }
            if (g == 0) {   // besum -> V partial (warp-uniform)
                float4 b4 = *reinterpret_cast<const float4*>(&besum_s[c * KC + 4 * q]);
                vacc[0] = ffma2(a0lo, make_float2(b4.x, b4.y), vacc[0]);
                vacc[0] = ffma2(a0hi, make_float2(b4.z, b4.w), vacc[0]);
                vacc[1] = ffma2(a1lo, make_float2(b4.x, b4.y), vacc[1]);
                vacc[1] = ffma2(a1hi, make_float2(b4.z, b4.w), vacc[1]);
            }
        }
        __syncthreads();
    }

    // write partials (coalesced: 32 consecutive rows per warp)
    #pragma unroll
    for (int m = 0; m < 2; m++) {
        int row = rowBase + r0 + 64 * m;
        #pragma unroll
        for (int n = 0; n < 8; n++) {
            int j = g * 8 + n;
            g_part[(kh * 33 + j) * ROWS_TOT + row] = acc[m][n].x + acc[m][n].y;
        }
        if (g == 0)
            g_part[(kh * 33 + 32) * ROWS_TOT + row] = vacc[m].x + vacc[m].y;
    }
}

// =======================================================================
// k1_reduce: sum the 2 k-half partials, epilogue, scatter to P / Ur / V.
// =======================================================================
__global__ __launch_bounds__(256)
void k1_reduce(const float* __restrict__ bc,
               const float* __restrict__ strength) {
    const int row = blockIdx.x * 256 + threadIdx.x;
    const int j = blockIdx.y;
    float v = g_part[j * ROWS_TOT + row] + g_part[(33 + j) * ROWS_TOT + row];
    const int b = row >> 12;
    const int s = row & (SN - 1);
    if (j < 16) {
        g_Pp[(b * SN + s) * RN + j] = (v + bc[j]) * strength[j];
    } else if (j < 32) {
        int r = j - 16;
        g_Ur[(((b * 8) + (r >> 1)) * SN + s) * 2 + (r & 1)] = v;
    } else {
        g_V[b * SN + s] = v;
    }
}

// =======================================================================
// kernel 2: bias[b,s,t] = sum_r P[b,s,r]*U[b,r,t] + V[b,t]
//   Rule-pair packing; per s-step 4 uniform LDS.128 + 32 FFMA2 + stream STG.
// =======================================================================
#define K2_TB 1024
#define K2_SB 64

__global__ __launch_bounds__(256, 2)
void k2_outer(float* __restrict__ out) {
    __shared__ __align__(16) float4 Ps[K2_SB * 4];   // 4KB

    const int tid = threadIdx.x;
    const int w = tid >> 5;
    const int l = tid & 31;
    const int b = blockIdx.z;
    const int sB = blockIdx.y * K2_SB;
    const int t = blockIdx.x * K2_TB + w * 128 + l * 4;

    Ps[tid] = reinterpret_cast<const float4*>(&g_Pp[(b * SN + sB) * RN])[tid];

    float2 u2[8][4];
    #pragma unroll
    for (int rp = 0; rp < 8; rp++) {
        const float4* ub = reinterpret_cast<const float4*>(
            &g_Ur[((size_t)(b * 8 + rp) * SN + t) * 2]);
        float4 lo = ub[0], hi = ub[1];
        u2[rp][0] = make_float2(lo.x, lo.y);
        u2[rp][1] = make_float2(lo.z, lo.w);
        u2[rp][2] = make_float2(hi.x, hi.y);
        u2[rp][3] = make_float2(hi.z, hi.w);
    }

    float4 v4 = *reinterpret_cast<const float4*>(&g_V[b * SN + t]);

    __syncthreads();

    float* orow = out + (size_t)(b * SN + sB) * SN + t;

    #pragma unroll 2
    for (int si = 0; si < K2_SB; si++) {
        float4 q0 = Ps[si * 4 + 0], q1 = Ps[si * 4 + 1];
        float4 q2 = Ps[si * 4 + 2], q3 = Ps[si * 4 + 3];
        float2 p2[8] = {
            make_float2(q0.x, q0.y), make_float2(q0.z, q0.w),
            make_float2(q1.x, q1.y), make_float2(q1.z, q1.w),
            make_float2(q2.x, q2.y), make_float2(q2.z, q2.w),
            make_float2(q3.x, q3.y), make_float2(q3.z, q3.w)
        };

        float2 a0 = make_float2(v4.x, 0.f), a1 = make_float2(v4.y, 0.f);
        float2 a2 = make_float2(v4.z, 0.f), a3 = make_float2(v4.w, 0.f);
        #pragma unroll
        for (int rp = 0; rp < 8; rp++) {
            a0 = ffma2(p2[rp], u2[rp][0], a0);
            a1 = ffma2(p2[rp], u2[rp][1], a1);
            a2 = ffma2(p2[rp], u2[rp][2], a2);
            a3 = ffma2(p2[rp], u2[rp][3], a3);
        }

        __stcs(reinterpret_cast<float4*>(orow + (size_t)si * SN),
               make_float4(a0.x + a0.y, a1.x + a1.y, a2.x + a2.y, a3.x + a3.y));
    }
}

// ---------------- launch ----------------
extern "C" void kernel_launch(void* const* d_in, const int* in_sizes, int n_in,
                              void* d_out, int out_size) {
    const float* hs       = (const float*)d_in[0];
    const float* wc       = (const float*)d_in[1];
    const float* bc       = (const float*)d_in[2];
    const float* we       = (const float*)d_in[3];
    const float* be       = (const float*)d_in[4];
    const float* strength = (const float*)d_in[5];
    float* out = (float*)d_out;

    k1_proj<<<dim3(ROWS_TOT / K1_BM, 2), 256>>>(hs, wc, we, be);
    k1_reduce<<<dim3(ROWS_TOT / 256, 33), 256>>>(bc, strength);
    k2_outer<<<dim3(SN / K2_TB, SN / K2_SB, BN), 256>>>(out);
}

// round 13
// speedup vs baseline: 1.0285x; 1.0166x over previous
#include <cuda_runtime.h>

// Problem constants
#define SN 4096
#define HN 1024
#define BN 4
#define RN 16
#define ROWS_TOT (BN * SN)     // 16384

// k1 tiling (split-K x4, BM=128, m=2 x n=8) -> 512 CTAs = 3.46/SM
#define K1_BM 128
#define KC 32
#define PT 36
#define KQ4 4
#define KQLEN (HN / KQ4)       // 256
#define NCH (KQLEN / KC)       // 8 chunks

// ---------------- scratch (device globals; no allocation) ----------------
__device__ float g_part[KQ4 * 33 * ROWS_TOT];  // split-K partials [kq][j][row]
__device__ float g_Pp[BN * SN * RN];           // plain P [b][s][r]
__device__ float g_Ur[BN * 8 * SN * 2];        // U r-pair interleaved [b][rp][t][2]
__device__ float g_V[BN * SN];                 // bias-term dot [b][t]

// packed f32x2 FMA
__device__ __forceinline__ float2 ffma2(float2 a, float2 b, float2 c) {
    float2 d;
    asm("fma.rn.f32x2 %0, %1, %2, %3;"
        : "=l"(*reinterpret_cast<unsigned long long*>(&d))
        : "l"(*reinterpret_cast<unsigned long long*>(&a)),
          "l"(*reinterpret_cast<unsigned long long*>(&b)),
          "l"(*reinterpret_cast<unsigned long long*>(&c)));
    return d;
}

__device__ __forceinline__ void cp16(void* smem_dst, const void* gmem_src) {
    unsigned sdst = (unsigned)__cvta_generic_to_shared(smem_dst);
    asm volatile("cp.async.cg.shared.global [%0], [%1], 16;"
                 :: "r"(sdst), "l"(gmem_src) : "memory");
}
__device__ __forceinline__ void cp_commit() {
    asm volatile("cp.async.commit_group;" ::: "memory");
}
__device__ __forceinline__ void cp_wait1() {
    asm volatile("cp.async.wait_group 1;" ::: "memory");
}
__device__ __forceinline__ void cp_wait0() {
    asm volatile("cp.async.wait_group 0;" ::: "memory");
}

// =======================================================================
// kernel 1: split-K x4 projection partials. grid (128, 4), 256 thr, occ 3.
//   512 CTAs -> ~3.5 CTAs/SM: occupancy finally resource-, not grid-limited.
//   Stage-before-wait pipeline; final chunk drains with wait_group 0.
// =======================================================================
__global__ __launch_bounds__(256, 3)
void k1_proj(const float* __restrict__ hs,
             const float* __restrict__ wc,
             const float* __restrict__ we,
             const float* __restrict__ be) {
    __shared__ float besum_s[KQLEN];
    __shared__ __align__(16) float As[2][K1_BM * PT];
    __shared__ __align__(16) float Ws[2][32 * PT];

    const int tid = threadIdx.x;
    const int x = tid & 31;
    const int wid = tid >> 5;
    const int rh = wid & 1;
    const int g = wid >> 1;              // n-group 0..3
    const int r0 = x + 32 * rh;          // base row (+64 for m=1)
    const int rowBase = blockIdx.x * K1_BM;
    const int kq = blockIdx.y;
    const int kOff = kq * KQLEN;

    // besum slice for this k-quarter (1 col per thread)
    {
        float s = 0.f;
        #pragma unroll
        for (int r = 0; r < RN; r++) s += be[r * HN + kOff + tid];
        besum_s[tid] = s;
    }

    auto stage = [&](int c, int buf) {
        #pragma unroll
        for (int i = 0; i < 4; i++) {
            int idx = tid + 256 * i;
            int row = idx >> 3, k4 = idx & 7;
            cp16(&As[buf][row * PT + k4 * 4],
                 &hs[(size_t)(rowBase + row) * HN + kOff + c * KC + k4 * 4]);
        }
        {
            int n = tid >> 3, k4 = tid & 7;
            const float* src = (n < 16)
                ? &wc[n * HN + kOff + c * KC + k4 * 4]
                : &we[(n - 16) * HN + kOff + c * KC + k4 * 4];
            cp16(&Ws[buf][n * PT + k4 * 4], src);
        }
        cp_commit();
    };

    float2 acc[2][8];
    #pragma unroll
    for (int m = 0; m < 2; m++)
        #pragma unroll
        for (int n = 0; n < 8; n++) acc[m][n] = make_float2(0.f, 0.f);
    float2 vacc[2] = {make_float2(0.f, 0.f), make_float2(0.f, 0.f)};

    stage(0, 0);

    for (int c = 0; c < NCH; c++) {
        if (c + 1 < NCH) {
            stage(c + 1, (c + 1) & 1);   // deep prefetch
            cp_wait1();                  // chunk c resident, c+1 in flight
        } else {
            cp_wait0();                  // final chunk: full drain
        }
        __syncthreads();
        const int buf = c & 1;

        #pragma unroll
        for (int q = 0; q < 8; q++) {                  // 4 k per q
            float4 a0 = *reinterpret_cast<const float4*>(&As[buf][r0 * PT + 4 * q]);
            float4 a1 = *reinterpret_cast<const float4*>(&As[buf][(r0 + 64) * PT + 4 * q]);
            float2 a0lo = make_float2(a0.x, a0.y), a0hi = make_float2(a0.z, a0.w);
            float2 a1lo = make_float2(a1.x, a1.y), a1hi = make_float2(a1.z, a1.w);

            #pragma unroll
            for (int nh = 0; nh < 2; nh++) {
                #pragma unroll
                for (int n = 0; n < 4; n++) {
                    float4 w4 = *reinterpret_cast<const float4*>(
                        &Ws[buf][(g * 8 + nh * 4 + n) * PT + 4 * q]);   // uniform
                    int nn = nh * 4 + n;
                    acc[0][nn] = ffma2(a0lo, make_float2(w4.x, w4.y), acc[0][nn]);
                    acc[0][nn] = ffma2(a0hi, make_float2(w4.z, w4.w), acc[0][nn]);
                    acc[1][nn] = ffma2(a1lo, make_float2(w4.x, w4.y), acc[1][nn]);
                    acc[1][nn] = ffma2(a1hi, make_float2(w4.z, w4.w), acc[1][nn]);
                }
            }
            if (g == 0) {   // besum -> V partial (warp-uniform)
                float4 b4 = *reinterpret_cast<const float4*>(&besum_s[c * KC + 4 * q]);
                vacc[0] = ffma2(a0lo, make_float2(b4.x, b4.y), vacc[0]);
                vacc[0] = ffma2(a0hi, make_float2(b4.z, b4.w), vacc[0]);
                vacc[1] = ffma2(a1lo, make_float2(b4.x, b4.y), vacc[1]);
                vacc[1] = ffma2(a1hi, make_float2(b4.z, b4.w), vacc[1]);
            }
        }
        __syncthreads();
    }

    // write partials (coalesced: 32 consecutive rows per warp)
    #pragma unroll
    for (int m = 0; m < 2; m++) {
        int row = rowBase + r0 + 64 * m;
        #pragma unroll
        for (int n = 0; n < 8; n++) {
            int j = g * 8 + n;
            g_part[(kq * 33 + j) * ROWS_TOT + row] = acc[m][n].x + acc[m][n].y;
        }
        if (g == 0)
            g_part[(kq * 33 + 32) * ROWS_TOT + row] = vacc[m].x + vacc[m].y;
    }
}

// =======================================================================
// k1_reduce: sum 4 split-K partials, epilogue, scatter to P / Ur / V.
// =======================================================================
__global__ __launch_bounds__(256)
void k1_reduce(const float* __restrict__ bc,
               const float* __restrict__ strength) {
    const int row = blockIdx.x * 256 + threadIdx.x;
    const int j = blockIdx.y;
    float v = 0.f;
    #pragma unroll
    for (int kq = 0; kq < KQ4; kq++)
        v += g_part[(kq * 33 + j) * ROWS_TOT + row];
    const int b = row >> 12;
    const int s = row & (SN - 1);
    if (j < 16) {
        g_Pp[(b * SN + s) * RN + j] = (v + bc[j]) * strength[j];
    } else if (j < 32) {
        int r = j - 16;
        g_Ur[(((b * 8) + (r >> 1)) * SN + s) * 2 + (r & 1)] = v;
    } else {
        g_V[b * SN + s] = v;
    }
}

// =======================================================================
// kernel 2: bias[b,s,t] = sum_r P[b,s,r]*U[b,r,t] + V[b,t]
//   Rule-pair packing; per s-step 4 uniform LDS.128 + 32 FFMA2 + stream STG.
// =======================================================================
#define K2_TB 1024
#define K2_SB 64

__global__ __launch_bounds__(256, 2)
void k2_outer(float* __restrict__ out) {
    __shared__ __align__(16) float4 Ps[K2_SB * 4];   // 4KB

    const int tid = threadIdx.x;
    const int w = tid >> 5;
    const int l = tid & 31;
    const int b = blockIdx.z;
    const int sB = blockIdx.y * K2_SB;
    const int t = blockIdx.x * K2_TB + w * 128 + l * 4;

    Ps[tid] = reinterpret_cast<const float4*>(&g_Pp[(b * SN + sB) * RN])[tid];

    float2 u2[8][4];
    #pragma unroll
    for (int rp = 0; rp < 8; rp++) {
        const float4* ub = reinterpret_cast<const float4*>(
            &g_Ur[((size_t)(b * 8 + rp) * SN + t) * 2]);
        float4 lo = ub[0], hi = ub[1];
        u2[rp][0] = make_float2(lo.x, lo.y);
        u2[rp][1] = make_float2(lo.z, lo.w);
        u2[rp][2] = make_float2(hi.x, hi.y);
        u2[rp][3] = make_float2(hi.z, hi.w);
    }

    float4 v4 = *reinterpret_cast<const float4*>(&g_V[b * SN + t]);

    __syncthreads();

    float* orow = out + (size_t)(b * SN + sB) * SN + t;

    #pragma unroll 2
    for (int si = 0; si < K2_SB; si++) {
        float4 q0 = Ps[si * 4 + 0], q1 = Ps[si * 4 + 1];
        float4 q2 = Ps[si * 4 + 2], q3 = Ps[si * 4 + 3];
        float2 p2[8] = {
            make_float2(q0.x, q0.y), make_float2(q0.z, q0.w),
            make_float2(q1.x, q1.y), make_float2(q1.z, q1.w),
            make_float2(q2.x, q2.y), make_float2(q2.z, q2.w),
            make_float2(q3.x, q3.y), make_float2(q3.z, q3.w)
        };

        float2 a0 = make_float2(v4.x, 0.f), a1 = make_float2(v4.y, 0.f);
        float2 a2 = make_float2(v4.z, 0.f), a3 = make_float2(v4.w, 0.f);
        #pragma unroll
        for (int rp = 0; rp < 8; rp++) {
            a0 = ffma2(p2[rp], u2[rp][0], a0);
            a1 = ffma2(p2[rp], u2[rp][1], a1);
            a2 = ffma2(p2[rp], u2[rp][2], a2);
            a3 = ffma2(p2[rp], u2[rp][3], a3);
        }

        __stcs(reinterpret_cast<float4*>(orow + (size_t)si * SN),
               make_float4(a0.x + a0.y, a1.x + a1.y, a2.x + a2.y, a3.x + a3.y));
    }
}

// ---------------- launch ----------------
extern "C" void kernel_launch(void* const* d_in, const int* in_sizes, int n_in,
                              void* d_out, int out_size) {
    const float* hs       = (const float*)d_in[0];
    const float* wc       = (const float*)d_in[1];
    const float* bc       = (const float*)d_in[2];
    const float* we       = (const float*)d_in[3];
    const float* be       = (const float*)d_in[4];
    const float* strength = (const float*)d_in[5];
    float* out = (float*)d_out;

    k1_proj<<<dim3(ROWS_TOT / K1_BM, KQ4), 256>>>(hs, wc, we, be);
    k1_reduce<<<dim3(ROWS_TOT / 256, 33), 256>>>(bc, strength);
    k2_outer<<<dim3(SN / K2_TB, SN / K2_SB, BN), 256>>>(out);
}

// round 15
// speedup vs baseline: 1.0942x; 1.0639x over previous
#include <cuda_runtime.h>
#include <cuda_bf16.h>
#include <cstdint>

// Problem constants
#define SN 4096
#define HN 1024
#define BN 4
#define RN 16
#define ROWS_TOT (BN * SN)     // 16384

// k1 mma.sync tiling
#define BM2 64                 // rows per CTA -> 256 CTAs
#define KC2 64                 // k per chunk
#define NCH2 (HN / KC2)        // 16
#define PB 72                  // smem pitch in bf16 (144B rows; ldmatrix conflict-free)

// ---------------- scratch (device globals; no allocation) ----------------
__device__ float g_Pp[BN * SN * RN];    // P [b][s][r]
__device__ float g_Ur[BN * 8 * SN * 2]; // U r-pair interleaved [b][rp][t][2]
__device__ float g_V[BN * SN];          // V [b][t]

// ---------------- helpers ----------------
__device__ __forceinline__ float2 ffma2(float2 a, float2 b, float2 c) {
    float2 d;
    asm("fma.rn.f32x2 %0, %1, %2, %3;"
        : "=l"(*reinterpret_cast<unsigned long long*>(&d))
        : "l"(*reinterpret_cast<unsigned long long*>(&a)),
          "l"(*reinterpret_cast<unsigned long long*>(&b)),
          "l"(*reinterpret_cast<unsigned long long*>(&c)));
    return d;
}

// split float4 -> bf16 hi pair + lo pair (memory order preserved)
__device__ __forceinline__ void cvt_split(float4 v, uint2& hp, uint2& lp) {
    __nv_bfloat162 h0 = __floats2bfloat162_rn(v.x, v.y);
    __nv_bfloat162 h1 = __floats2bfloat162_rn(v.z, v.w);
    float2 f0 = __bfloat1622float2(h0);
    float2 f1 = __bfloat1622float2(h1);
    __nv_bfloat162 l0 = __floats2bfloat162_rn(v.x - f0.x, v.y - f0.y);
    __nv_bfloat162 l1 = __floats2bfloat162_rn(v.z - f1.x, v.w - f1.y);
    hp.x = *reinterpret_cast<uint32_t*>(&h0);
    hp.y = *reinterpret_cast<uint32_t*>(&h1);
    lp.x = *reinterpret_cast<uint32_t*>(&l0);
    lp.y = *reinterpret_cast<uint32_t*>(&l1);
}

__device__ __forceinline__ void ldmx4(uint32_t* r, uint32_t addr) {
    asm volatile("ldmatrix.sync.aligned.m8n8.x4.shared.b16 {%0,%1,%2,%3}, [%4];"
                 : "=r"(r[0]), "=r"(r[1]), "=r"(r[2]), "=r"(r[3]) : "r"(addr));
}

__device__ __forceinline__ void mma_bf16(float* c, const uint32_t* a,
                                         uint32_t b0, uint32_t b1) {
    asm volatile("mma.sync.aligned.m16n8k16.row.col.f32.bf16.bf16.f32 "
                 "{%0,%1,%2,%3}, {%4,%5,%6,%7}, {%8,%9}, {%0,%1,%2,%3};"
                 : "+f"(c[0]), "+f"(c[1]), "+f"(c[2]), "+f"(c[3])
                 : "r"(a[0]), "r"(a[1]), "r"(a[2]), "r"(a[3]), "r"(b0), "r"(b1));
}

// =======================================================================
// k1_mma: P/U/V projection via mma.sync bf16, hi/lo split (3 products).
//   grid 256, block 256. Warp tile m16 x n24/n16; N padded 48 (real 33).
// =======================================================================
__global__ __launch_bounds__(256)
void k1_mma(const float* __restrict__ hs,
            const float* __restrict__ wc,
            const float* __restrict__ we,
            const float* __restrict__ be,
            const float* __restrict__ bc,
            const float* __restrict__ strength) {
    __shared__ __align__(16) __nv_bfloat16 sAhi[BM2 * PB], sAlo[BM2 * PB];
    __shared__ __align__(16) __nv_bfloat16 sWhi[48 * PB],  sWlo[48 * PB];

    const int tid = threadIdx.x;
    const int wid = tid >> 5;
    const int lane = tid & 31;
    const int rowBase = blockIdx.x * BM2;

    const uint32_t uAhi = (uint32_t)__cvta_generic_to_shared(sAhi);
    const uint32_t uAlo = (uint32_t)__cvta_generic_to_shared(sAlo);
    const uint32_t uWhi = (uint32_t)__cvta_generic_to_shared(sWhi);
    const uint32_t uWlo = (uint32_t)__cvta_generic_to_shared(sWlo);

    // zero W smem once (rows 33-47 must stay zero; rows 0-32 rewritten per chunk)
    {
        uint32_t* wz0 = reinterpret_cast<uint32_t*>(sWhi);
        uint32_t* wz1 = reinterpret_cast<uint32_t*>(sWlo);
        for (int i = tid; i < 48 * PB / 2; i += 256) { wz0[i] = 0u; wz1[i] = 0u; }
    }

    // staging roles
    const int arow = tid >> 2, aq = tid & 3;           // A: 64 rows x 4 quarters
    const int wn = tid >> 2, wq = tid & 3;             // W: rows 0-31 (tid<128)
    const float* asrc = hs + (size_t)(rowBase + arow) * HN;
    const float* wsrc = (wn < 16) ? (wc + wn * HN) : (we + (wn - 16) * HN);
    const int bcol = tid - 192;                        // besum: tid>=192, cols 0-63

    float4 av[4], wv[4];
    float bs = 0.f;

    auto ldg = [&](int c) {
        const float4* a4 = reinterpret_cast<const float4*>(asrc + c * KC2 + aq * 16);
        #pragma unroll
        for (int j = 0; j < 4; j++) av[j] = a4[j];
        if (tid < 128) {
            const float4* w4 = reinterpret_cast<const float4*>(wsrc + c * KC2 + wq * 16);
            #pragma unroll
            for (int j = 0; j < 4; j++) wv[j] = w4[j];
        }
        if (tid >= 192) {
            bs = 0.f;
            #pragma unroll
            for (int r = 0; r < RN; r++) bs += be[r * HN + c * KC2 + bcol];
        }
    };

    auto sts = [&]() {
        #pragma unroll
        for (int j = 0; j < 4; j++) {
            uint2 hp, lp;
            cvt_split(av[j], hp, lp);
            int off = arow * PB + aq * 16 + j * 4;
            *reinterpret_cast<uint2*>(sAhi + off) = hp;
            *reinterpret_cast<uint2*>(sAlo + off) = lp;
        }
        if (tid < 128) {
            #pragma unroll
            for (int j = 0; j < 4; j++) {
                uint2 hp, lp;
                cvt_split(wv[j], hp, lp);
                int off = wn * PB + wq * 16 + j * 4;
                *reinterpret_cast<uint2*>(sWhi + off) = hp;
                *reinterpret_cast<uint2*>(sWlo + off) = lp;
            }
        }
        if (tid >= 192) {
            __nv_bfloat16 h = __float2bfloat16_rn(bs);
            __nv_bfloat16 l = __float2bfloat16_rn(bs - __bfloat162float(h));
            sWhi[32 * PB + bcol] = h;
            sWlo[32 * PB + bcol] = l;
        }
    };

    // warp tile mapping
    const int mgrp = wid & 3, ngrp = wid >> 2;
    const int nt = (ngrp == 0) ? 3 : 2;                // tiles {0,8,16} / {24,32}
    const int mbase = mgrp * 16;
    const int arow_l = mbase + (lane & 15);
    const int acol = ((lane >> 4) & 1) * 8;
    const uint32_t uBsel = (lane < 16) ? uWhi : uWlo;  // hi tiles lanes 0-15, lo 16-31
    const int bro = lane & 7;
    const int bco = ((lane >> 3) & 1) * 8;

    float cacc[3][4];
    #pragma unroll
    for (int j = 0; j < 3; j++)
        #pragma unroll
        for (int i = 0; i < 4; i++) cacc[j][i] = 0.f;

    ldg(0);
    sts();
    __syncthreads();

    for (int c = 0; c < NCH2; c++) {
        if (c + 1 < NCH2) ldg(c + 1);      // global prefetch overlaps mma

        #pragma unroll
        for (int ks = 0; ks < KC2 / 16; ks++) {
            const int k0 = ks * 16;
            uint32_t ah[4], al[4];
            ldmx4(ah, uAhi + (uint32_t)(arow_l * PB + k0 + acol) * 2);
            ldmx4(al, uAlo + (uint32_t)(arow_l * PB + k0 + acol) * 2);
            #pragma unroll
            for (int j = 0; j < 3; j++) {
                if (j >= nt) break;
                const int nb = ngrp * 24 + j * 8;
                uint32_t bb[4];                 // {bhi0,bhi1,blo0,blo1}
                ldmx4(bb, uBsel + (uint32_t)((nb + bro) * PB + k0 + bco) * 2);
                mma_bf16(cacc[j], ah, bb[0], bb[1]);   // Ahi*Whi
                mma_bf16(cacc[j], al, bb[0], bb[1]);   // Alo*Whi
                mma_bf16(cacc[j], ah, bb[2], bb[3]);   // Ahi*Wlo
            }
        }
        __syncthreads();
        if (c + 1 < NCH2) sts();
        __syncthreads();
    }

    // ---- epilogue: scatter C fragments to P / Ur / V
    {
        const int row = rowBase + mbase + (lane >> 2);
        const int b = row >> 12;
        const int s = row & (SN - 1);
        #pragma unroll
        for (int j = 0; j < 3; j++) {
            if (j >= nt) break;
            const int n0 = ngrp * 24 + j * 8 + 2 * (lane & 3);
            const float* cj = cacc[j];
            if (n0 < 16) {
                float b0 = bc[n0], b1 = bc[n0 + 1];
                float s0 = strength[n0], s1 = strength[n0 + 1];
                float* p0 = &g_Pp[(size_t)(b * SN + s) * RN + n0];
                float* p1 = &g_Pp[(size_t)(b * SN + s + 8) * RN + n0];
                *reinterpret_cast<float2*>(p0) =
                    make_float2((cj[0] + b0) * s0, (cj[1] + b1) * s1);
                *reinterpret_cast<float2*>(p1) =
                    make_float2((cj[2] + b0) * s0, (cj[3] + b1) * s1);
            } else if (n0 < 32) {
                const int rp = (n0 - 16) >> 1;
                *reinterpret_cast<float2*>(
                    &g_Ur[((size_t)(b * 8 + rp) * SN + s) * 2]) =
                    make_float2(cj[0], cj[1]);
                *reinterpret_cast<float2*>(
                    &g_Ur[((size_t)(b * 8 + rp) * SN + s + 8) * 2]) =
                    make_float2(cj[2], cj[3]);
            } else if (n0 == 32) {
                g_V[b * SN + s] = cj[0];
                g_V[b * SN + s + 8] = cj[2];
            }
        }
    }
}

// =======================================================================
// kernel 2: bias[b,s,t] = sum_r P[b,s,r]*U[b,r,t] + V[b,t]  (unchanged)
// =======================================================================
#define K2_TB 1024
#define K2_SB 64

__global__ __launch_bounds__(256, 2)
void k2_outer(float* __restrict__ out) {
    __shared__ __align__(16) float4 Ps[K2_SB * 4];   // 4KB

    const int tid = threadIdx.x;
    const int w = tid >> 5;
    const int l = tid & 31;
    const int b = blockIdx.z;
    const int sB = blockIdx.y * K2_SB;
    const int t = blockIdx.x * K2_TB + w * 128 + l * 4;

    Ps[tid] = reinterpret_cast<const float4*>(&g_Pp[(size_t)(b * SN + sB) * RN])[tid];

    float2 u2[8][4];
    #pragma unroll
    for (int rp = 0; rp < 8; rp++) {
        const float4* ub = reinterpret_cast<const float4*>(
            &g_Ur[((size_t)(b * 8 + rp) * SN + t) * 2]);
        float4 lo = ub[0], hi = ub[1];
        u2[rp][0] = make_float2(lo.x, lo.y);
        u2[rp][1] = make_float2(lo.z, lo.w);
        u2[rp][2] = make_float2(hi.x, hi.y);
        u2[rp][3] = make_float2(hi.z, hi.w);
    }

    float4 v4 = *reinterpret_cast<const float4*>(&g_V[b * SN + t]);

    __syncthreads();

    float* orow = out + (size_t)(b * SN + sB) * SN + t;

    #pragma unroll 2
    for (int si = 0; si < K2_SB; si++) {
        float4 q0 = Ps[si * 4 + 0], q1 = Ps[si * 4 + 1];
        float4 q2 = Ps[si * 4 + 2], q3 = Ps[si * 4 + 3];
        float2 p2[8] = {
            make_float2(q0.x, q0.y), make_float2(q0.z, q0.w),
            make_float2(q1.x, q1.y), make_float2(q1.z, q1.w),
            make_float2(q2.x, q2.y), make_float2(q2.z, q2.w),
            make_float2(q3.x, q3.y), make_float2(q3.z, q3.w)
        };

        float2 a0 = make_float2(v4.x, 0.f), a1 = make_float2(v4.y, 0.f);
        float2 a2 = make_float2(v4.z, 0.f), a3 = make_float2(v4.w, 0.f);
        #pragma unroll
        for (int rp = 0; rp < 8; rp++) {
            a0 = ffma2(p2[rp], u2[rp][0], a0);
            a1 = ffma2(p2[rp], u2[rp][1], a1);
            a2 = ffma2(p2[rp], u2[rp][2], a2);
            a3 = ffma2(p2[rp], u2[rp][3], a3);
        }

        __stcs(reinterpret_cast<float4*>(orow + (size_t)si * SN),
               make_float4(a0.x + a0.y, a1.x + a1.y, a2.x + a2.y, a3.x + a3.y));
    }
}

// ---------------- launch ----------------
extern "C" void kernel_launch(void* const* d_in, const int* in_sizes, int n_in,
                              void* d_out, int out_size) {
    const float* hs       = (const float*)d_in[0];
    const float* wc       = (const float*)d_in[1];
    const float* bc       = (const float*)d_in[2];
    const float* we       = (const float*)d_in[3];
    const float* be       = (const float*)d_in[4];
    const float* strength = (const float*)d_in[5];
    float* out = (float*)d_out;

    k1_mma<<<ROWS_TOT / BM2, 256>>>(hs, wc, we, be, bc, strength);
    k2_outer<<<dim3(SN / K2_TB, SN / K2_SB, BN), 256>>>(out);
}